// round 11
// baseline (speedup 1.0000x reference)
#include <cuda_runtime.h>
#include <cuda_bf16.h>

// Problem constants: N=100000, E=3200000, F_in=128, H=25, C=40
#define MAXN 100000
#define MAXE 3200000
#define FIN  128
#define H1   25
#define H1P  32        // padded pitch: 128B rows (h1p, ap)
#define C2   40

// Scratch (__device__ globals — allocation-free rule; zero-init at load)
__device__ float g_dinv[MAXN];
__device__ int   g_cnt [MAXN];
__device__ int   g_row [MAXN + 1];
__device__ int   g_cur [MAXN];
__device__ int   g_psum[128];
__device__ int   g_poff[128];
__device__ int2  g_edge[MAXE];         // build: {src, w_bits} -> fold: {src, norm_bits}
__device__ float g_h1p [MAXN * H1P];   // x @ W1, padded (pad cols stay 0)
__device__ float g_ap  [MAXN * H1P];   // relu(agg1 + self + b1), pad cols written 0
__device__ int   g_is64;

// ---------------------------------------------------------------------------
// detect dtype + zero histogram, one kernel
__global__ void detect_init_kernel(const int* __restrict__ ei, int N) {
    int i = blockIdx.x * blockDim.x + threadIdx.x;
    if (i < N) g_cnt[i] = 0;
    if (blockIdx.x == 0 && threadIdx.x == 0) {
        int all0 = 1;
        for (int k = 0; k < 64; k++)
            if (ei[2 * k + 1] != 0) { all0 = 0; break; }
        g_is64 = all0;
    }
}

__device__ __forceinline__ int ld_node(const int* __restrict__ ei32,
                                       long long pos, int is64) {
    return ei32[is64 ? (pos << 1) : pos];   // little-endian low word
}

// in-degree histogram — int atomics only
__global__ void cnt_kernel(const int* __restrict__ ei32, int E) {
    int e = blockIdx.x * blockDim.x + threadIdx.x;
    if (e >= E) return;
    int d = ld_node(ei32, (long long)E + e, g_is64);
    atomicAdd(&g_cnt[d], 1);
}

// ---------------------------------------------------------------------------
// 3-phase scan of g_cnt -> g_row (exclusive), g_cur copy, g_row[N]=E.
__global__ void scan_local(int N) {
    __shared__ int sh[1024];
    int i = blockIdx.x * 1024 + threadIdx.x;
    int v = (i < N) ? g_cnt[i] : 0;
    sh[threadIdx.x] = v;
    __syncthreads();
    int acc = v;
    for (int off = 1; off < 1024; off <<= 1) {
        int p = (threadIdx.x >= off) ? sh[threadIdx.x - off] : 0;
        __syncthreads();
        acc += p;
        sh[threadIdx.x] = acc;
        __syncthreads();
    }
    if (i < N) g_row[i] = acc - v;
    if (threadIdx.x == 1023) g_psum[blockIdx.x] = acc;
}

__global__ void scan_tops(int NB, int N, int E) {
    __shared__ int sh[128];
    int t = threadIdx.x;
    int v = (t < NB) ? g_psum[t] : 0;
    sh[t] = v;
    __syncthreads();
    int acc = v;
    for (int off = 1; off < 128; off <<= 1) {
        int p = (t >= off) ? sh[t - off] : 0;
        __syncthreads();
        acc += p;
        sh[t] = acc;
        __syncthreads();
    }
    if (t < NB) g_poff[t] = acc - v;
    if (t == 0) g_row[N] = E;
}

__global__ void scan_add(int N) {
    int i = blockIdx.x * blockDim.x + threadIdx.x;
    if (i >= N) return;
    int r = g_row[i] + g_poff[i >> 10];
    g_row[i] = r;
    g_cur[i] = r;
}

// Bucket-scatter raw edges {src, w}. NO dinv reads here.
__global__ void build_kernel(const int* __restrict__ ei32,
                             const float* __restrict__ w, int E) {
    int e = blockIdx.x * blockDim.x + threadIdx.x;
    if (e >= E) return;
    int is64 = g_is64;
    int s = ld_node(ei32, e, is64);
    int d = ld_node(ei32, (long long)E + e, is64);
    int pos = atomicAdd(&g_cur[d], 1);
    g_edge[pos] = make_int2(s, __float_as_int(w[e]));
}

// Streaming degree: warp per node, coalesced sum of row weights -> dinv.
// deg = sum(w) + 1 (self-loop). deg > 0 always, so rsqrt is safe.
#define WPBD 8
__global__ void deg_kernel(int N) {
    int warp = threadIdx.x >> 5;
    int lane = threadIdx.x & 31;
    int i = blockIdx.x * WPBD + warp;
    if (i >= N) return;
    int j0 = g_row[i], j1 = g_row[i + 1];
    float s = 0.0f;
    for (int j = j0 + lane; j < j1; j += 32)
        s += __int_as_float(__ldg(&g_edge[j]).y);
    #pragma unroll
    for (int off = 16; off > 0; off >>= 1)
        s += __shfl_xor_sync(0xffffffffu, s, off);
    if (lane == 0) g_dinv[i] = rsqrtf(s + 1.0f);
}

// Norm fold: warp per node, coalesced int2 rewrite; only dinv[src] is random.
#define WPBF 8
__global__ void fold_kernel(int N) {
    int warp = threadIdx.x >> 5;
    int lane = threadIdx.x & 31;
    int i = blockIdx.x * WPBF + warp;
    if (i >= N) return;
    float dvI = g_dinv[i];
    int j0 = g_row[i], j1 = g_row[i + 1];
    for (int j = j0 + lane; j < j1; j += 32) {
        int2 e = g_edge[j];
        float nm = __ldg(&g_dinv[e.x]) * __int_as_float(e.y) * dvI;
        g_edge[j] = make_int2(e.x, __float_as_int(nm));
    }
}

// ---------------------------------------------------------------------------
// GEMM1: h1p[N,32] = x[N,128] @ W1[128,25]. 4 rows x 5 cols per thread.
#define G1_TB   320
#define G1_RPB  256
__global__ void gemm1_kernel(const float* __restrict__ x,
                             const float* __restrict__ W1, int N) {
    __shared__ float ws[FIN * H1];
    for (int i = threadIdx.x; i < FIN * H1; i += G1_TB) ws[i] = W1[i];
    __syncthreads();

    int rowGroup = threadIdx.x / 5;
    int colGroup = threadIdx.x % 5;
    int r0 = blockIdx.x * G1_RPB + rowGroup * 4;
    int c0 = colGroup * 5;

    float acc[4][5];
    #pragma unroll
    for (int a = 0; a < 4; a++)
        #pragma unroll
        for (int b = 0; b < 5; b++) acc[a][b] = 0.0f;

    #pragma unroll 4
    for (int kb = 0; kb < FIN / 4; kb++) {
        float xr[4][4];
        #pragma unroll
        for (int a = 0; a < 4; a++) {
            int r = r0 + a;
            float4 v = (r < N) ? __ldg((const float4*)(x + (size_t)r * FIN) + kb)
                               : make_float4(0.f, 0.f, 0.f, 0.f);
            xr[a][0] = v.x; xr[a][1] = v.y; xr[a][2] = v.z; xr[a][3] = v.w;
        }
        #pragma unroll
        for (int t = 0; t < 4; t++) {
            int k = kb * 4 + t;
            float wv[5];
            #pragma unroll
            for (int b = 0; b < 5; b++) wv[b] = ws[k * H1 + c0 + b];
            #pragma unroll
            for (int a = 0; a < 4; a++)
                #pragma unroll
                for (int b = 0; b < 5; b++) acc[a][b] += xr[a][t] * wv[b];
        }
    }

    #pragma unroll
    for (int a = 0; a < 4; a++) {
        int r = r0 + a;
        if (r >= N) break;
        #pragma unroll
        for (int b = 0; b < 5; b++)
            g_h1p[(size_t)r * H1P + c0 + b] = acc[a][b];
    }
}

// ---------------------------------------------------------------------------
// Layer-1: CSR aggregate (rolled, norms precomputed) + self + b1 + ReLU -> ap.
#define WPB1 8
__global__ void agg1_kernel(const float* __restrict__ b1, int N) {
    __shared__ float b1s[H1];
    if (threadIdx.x < H1) b1s[threadIdx.x] = b1[threadIdx.x];
    __syncthreads();

    int warp = threadIdx.x >> 5;
    int lane = threadIdx.x & 31;
    int i = blockIdx.x * WPB1 + warp;
    if (i >= N) return;

    float dv = g_dinv[i];
    float acc = dv * dv * __ldg(&g_h1p[(size_t)i * H1P + lane]);

    int j0 = g_row[i], j1 = g_row[i + 1];
    for (int j = j0; j < j1; j++) {
        int2 pr = __ldg(&g_edge[j]);                         // broadcast 8B
        acc += __int_as_float(pr.y) * __ldg(&g_h1p[(size_t)pr.x * H1P + lane]);
    }

    float a = 0.0f;
    if (lane < H1) {
        a = acc + b1s[lane];
        a = a > 0.0f ? a : 0.0f;
    }
    g_ap[(size_t)i * H1P + lane] = a;                        // full 128B store
}

// ---------------------------------------------------------------------------
// Layer-2: aggregate 25-dim ap (128B rows), then GEMM2 + b2 + log-softmax.
#define WPB2 8
__global__ void agg2_kernel(float* __restrict__ out,
                            const float* __restrict__ W2,
                            const float* __restrict__ b2, int N) {
    __shared__ float w2s[H1 * C2];
    __shared__ float b2s[C2];
    __shared__ float sa[WPB2][H1];
    for (int k = threadIdx.x; k < H1 * C2; k += WPB2 * 32) w2s[k] = W2[k];
    if (threadIdx.x < C2) b2s[threadIdx.x] = b2[threadIdx.x];
    __syncthreads();

    int warp = threadIdx.x >> 5;
    int lane = threadIdx.x & 31;
    int i = blockIdx.x * WPB2 + warp;
    if (i >= N) return;

    float dv = g_dinv[i];
    float acc = dv * dv * __ldg(&g_ap[(size_t)i * H1P + lane]);

    int j0 = g_row[i], j1 = g_row[i + 1];
    for (int j = j0; j < j1; j++) {
        int2 pr = __ldg(&g_edge[j]);                         // {src, norm_bits}
        acc += __int_as_float(pr.y) * __ldg(&g_ap[(size_t)pr.x * H1P + lane]);
    }

    if (lane < H1) sa[warp][lane] = acc;
    __syncwarp();

    const float* a = sa[warp];
    bool has1 = (lane < C2 - 32);
    float o0 = b2s[lane];
    float o1 = has1 ? b2s[lane + 32] : 0.0f;
    #pragma unroll
    for (int k = 0; k < H1; k++) {
        float av = a[k];
        o0 += av * w2s[k * C2 + lane];
        if (has1) o1 += av * w2s[k * C2 + lane + 32];
    }

    float m = fmaxf(o0, has1 ? o1 : -3.4e38f);
    #pragma unroll
    for (int off = 16; off > 0; off >>= 1)
        m = fmaxf(m, __shfl_xor_sync(0xffffffffu, m, off));
    float s = __expf(o0 - m) + (has1 ? __expf(o1 - m) : 0.0f);
    #pragma unroll
    for (int off = 16; off > 0; off >>= 1)
        s += __shfl_xor_sync(0xffffffffu, s, off);
    float lse = m + logf(s);

    out[(size_t)i * C2 + lane] = o0 - lse;
    if (has1) out[(size_t)i * C2 + 32 + lane] = o1 - lse;
}

// ---------------------------------------------------------------------------
extern "C" void kernel_launch(void* const* d_in, const int* in_sizes, int n_in,
                              void* d_out, int out_size) {
    const float* x    = (const float*)d_in[0];
    const int*   ei32 = (const int*)d_in[1];
    const float* w    = (const float*)d_in[2];
    const float* W1   = (const float*)d_in[3];
    const float* b1   = (const float*)d_in[4];
    const float* W2   = (const float*)d_in[5];
    const float* b2   = (const float*)d_in[6];
    float* out = (float*)d_out;

    int E = in_sizes[2];
    int N = in_sizes[0] / FIN;

    const int TB = 256;
    int gridE = (E + TB - 1) / TB;
    int gridN = (N + TB - 1) / TB;
    int NB    = (N + 1023) / 1024;
    int gridW = (N + 7) / 8;       // warp-per-node kernels (8 warps/block)

    detect_init_kernel<<<gridN, TB>>>(ei32, N);
    cnt_kernel<<<gridE, TB>>>(ei32, E);
    gemm1_kernel<<<(N + G1_RPB - 1) / G1_RPB, G1_TB>>>(x, W1, N);
    scan_local<<<NB, 1024>>>(N);
    scan_tops<<<1, 128>>>(NB, N, E);
    scan_add<<<gridN, TB>>>(N);
    build_kernel<<<gridE, TB>>>(ei32, w, E);
    deg_kernel<<<gridW, WPBD * 32>>>(N);
    fold_kernel<<<gridW, WPBF * 32>>>(N);
    agg1_kernel<<<gridW, WPB1 * 32>>>(b1, N);
    agg2_kernel<<<gridW, WPB2 * 32>>>(out, W2, b2, N);
}

// round 14
// speedup vs baseline: 1.0791x; 1.0791x over previous
#include <cuda_runtime.h>
#include <cuda_bf16.h>

// Problem constants: N=100000, E=3200000, F_in=128, H=25, C=40
#define MAXN 100000
#define MAXE 3200000
#define FIN  128
#define H1   25
#define H1P  32        // padded pitch: 128B rows (h1p, ap) = 8 float4
#define C2   40

// Scratch (__device__ globals — allocation-free rule; zero-init at load)
__device__ float g_deg [MAXN];
__device__ float g_dinv[MAXN];
__device__ int   g_cnt [MAXN];
__device__ int   g_row [MAXN + 1];
__device__ int   g_cur [MAXN];
__device__ int   g_psum[128];
__device__ int   g_poff[128];
__device__ int2  g_edge[MAXE];         // {src, float_bits(norm)} — norm folded at build
__device__ float g_h1p [MAXN * H1P];   // x @ W1, padded (pad cols stay 0)
__device__ float g_ap  [MAXN * H1P];   // relu(agg1 + self + b1), pads written 0
__device__ int   g_is64;

// ---------------------------------------------------------------------------
// launch #0: detect dtype + init deg/cnt
__global__ void detect_init_kernel(const int* __restrict__ ei, int N) {
    int i = blockIdx.x * blockDim.x + threadIdx.x;
    if (i < N) { g_cnt[i] = 0; g_deg[i] = 1.0f; }
    if (blockIdx.x == 0 && threadIdx.x == 0) {
        int all0 = 1;
        for (int k = 0; k < 64; k++)
            if (ei[2 * k + 1] != 0) { all0 = 0; break; }
        g_is64 = all0;
    }
}

__device__ __forceinline__ int ld_node(const int* __restrict__ ei32,
                                       long long pos, int is64) {
    return ei32[is64 ? (pos << 1) : pos];   // little-endian low word
}

// launch #3 (ncu capture slot): degree + count histogram
__global__ void degree_kernel(const int* __restrict__ ei32,
                              const float* __restrict__ w, int E) {
    int e = blockIdx.x * blockDim.x + threadIdx.x;
    if (e >= E) return;
    int is64 = g_is64;
    int d = ld_node(ei32, (long long)E + e, is64);
    atomicAdd(&g_deg[d], w[e]);
    atomicAdd(&g_cnt[d], 1);
}

__global__ void dinv_kernel(int N) {
    int i = blockIdx.x * blockDim.x + threadIdx.x;
    if (i >= N) return;
    float d = g_deg[i];
    g_dinv[i] = (d > 0.0f) ? rsqrtf(d) : 0.0f;
}

// ---------------------------------------------------------------------------
// 3-phase scan of g_cnt -> g_row (exclusive), g_cur copy, g_row[N]=E.
__global__ void scan_local(int N) {
    __shared__ int sh[1024];
    int i = blockIdx.x * 1024 + threadIdx.x;
    int v = (i < N) ? g_cnt[i] : 0;
    sh[threadIdx.x] = v;
    __syncthreads();
    int acc = v;
    for (int off = 1; off < 1024; off <<= 1) {
        int p = (threadIdx.x >= off) ? sh[threadIdx.x - off] : 0;
        __syncthreads();
        acc += p;
        sh[threadIdx.x] = acc;
        __syncthreads();
    }
    if (i < N) g_row[i] = acc - v;
    if (threadIdx.x == 1023) g_psum[blockIdx.x] = acc;
}

__global__ void scan_tops(int NB, int N, int E) {
    __shared__ int sh[128];
    int t = threadIdx.x;
    int v = (t < NB) ? g_psum[t] : 0;
    sh[t] = v;
    __syncthreads();
    int acc = v;
    for (int off = 1; off < 128; off <<= 1) {
        int p = (t >= off) ? sh[t - off] : 0;
        __syncthreads();
        acc += p;
        sh[t] = acc;
        __syncthreads();
    }
    if (t < NB) g_poff[t] = acc - v;
    if (t == 0) g_row[N] = E;
}

__global__ void scan_add(int N) {
    int i = blockIdx.x * blockDim.x + threadIdx.x;
    if (i >= N) return;
    int r = g_row[i] + g_poff[i >> 10];
    g_row[i] = r;
    g_cur[i] = r;
}

// Bucket-scatter edges; norm folded here (R8-proven form).
__global__ void build_kernel(const int* __restrict__ ei32,
                             const float* __restrict__ w, int E) {
    int e = blockIdx.x * blockDim.x + threadIdx.x;
    if (e >= E) return;
    int is64 = g_is64;
    int s = ld_node(ei32, e, is64);
    int d = ld_node(ei32, (long long)E + e, is64);
    float nm = g_dinv[s] * w[e] * g_dinv[d];
    int pos = atomicAdd(&g_cur[d], 1);
    g_edge[pos] = make_int2(s, __float_as_int(nm));
}

// ---------------------------------------------------------------------------
// GEMM1: h1p[rows r0..r1) = x @ W1. 4 rows x 5 cols per thread. Split-launch.
#define G1_TB   320
#define G1_RPB  256
__global__ void gemm1_kernel(const float* __restrict__ x,
                             const float* __restrict__ W1, int r_base, int r_end) {
    __shared__ float ws[FIN * H1];
    for (int i = threadIdx.x; i < FIN * H1; i += G1_TB) ws[i] = W1[i];
    __syncthreads();

    int rowGroup = threadIdx.x / 5;
    int colGroup = threadIdx.x % 5;
    int r0 = r_base + blockIdx.x * G1_RPB + rowGroup * 4;
    int c0 = colGroup * 5;

    float acc[4][5];
    #pragma unroll
    for (int a = 0; a < 4; a++)
        #pragma unroll
        for (int b = 0; b < 5; b++) acc[a][b] = 0.0f;

    #pragma unroll 4
    for (int kb = 0; kb < FIN / 4; kb++) {
        float xr[4][4];
        #pragma unroll
        for (int a = 0; a < 4; a++) {
            int r = r0 + a;
            float4 v = (r < r_end) ? __ldg((const float4*)(x + (size_t)r * FIN) + kb)
                                   : make_float4(0.f, 0.f, 0.f, 0.f);
            xr[a][0] = v.x; xr[a][1] = v.y; xr[a][2] = v.z; xr[a][3] = v.w;
        }
        #pragma unroll
        for (int t = 0; t < 4; t++) {
            int k = kb * 4 + t;
            float wv[5];
            #pragma unroll
            for (int b = 0; b < 5; b++) wv[b] = ws[k * H1 + c0 + b];
            #pragma unroll
            for (int a = 0; a < 4; a++)
                #pragma unroll
                for (int b = 0; b < 5; b++) acc[a][b] += xr[a][t] * wv[b];
        }
    }

    #pragma unroll
    for (int a = 0; a < 4; a++) {
        int r = r0 + a;
        if (r >= r_end) break;
        #pragma unroll
        for (int b = 0; b < 5; b++)
            g_h1p[(size_t)r * H1P + c0 + b] = acc[a][b];
    }
}

// ---------------------------------------------------------------------------
// Layer-1 aggregate, grouped-float4: warp = 4 edge-groups x 8 lanes.
// Per iteration: 4 edges, one LDG.64 (edges) + one LDG.128/lane (rows).
#define WPB1 8
__global__ void agg1_kernel(const float* __restrict__ b1, int N) {
    __shared__ __align__(16) float b1s[32];
    if (threadIdx.x < 32)
        b1s[threadIdx.x] = (threadIdx.x < H1) ? b1[threadIdx.x] : 0.0f;
    __syncthreads();

    int warp = threadIdx.x >> 5;
    int lane = threadIdx.x & 31;
    int grp  = lane >> 3;        // edge group 0..3
    int sub  = lane & 7;         // feature quad 0..7
    int i = blockIdx.x * WPB1 + warp;
    if (i >= N) return;

    const float4* h4 = (const float4*)g_h1p;   // pitch 8 float4 per row
    float4 acc = make_float4(0.f, 0.f, 0.f, 0.f);
    if (grp == 0) {
        float dv = g_dinv[i];
        float d2 = dv * dv;
        float4 sv = __ldg(&h4[(size_t)i * 8 + sub]);
        acc.x = d2 * sv.x; acc.y = d2 * sv.y; acc.z = d2 * sv.z; acc.w = d2 * sv.w;
    }

    int j0 = g_row[i], j1 = g_row[i + 1];
    for (int jb = j0; jb < j1; jb += 4) {
        int je = jb + grp;
        int2 pr = (je < j1) ? __ldg(&g_edge[je]) : make_int2(0, 0);
        float nm = __int_as_float(pr.y);                    // 0 for OOB
        float4 v = __ldg(&h4[(size_t)pr.x * 8 + sub]);
        acc.x += nm * v.x; acc.y += nm * v.y;
        acc.z += nm * v.z; acc.w += nm * v.w;
    }

    // reduce across the 4 groups (lanes sub, sub+8, sub+16, sub+24)
    #pragma unroll
    for (int off = 8; off <= 16; off <<= 1) {
        acc.x += __shfl_xor_sync(0xffffffffu, acc.x, off);
        acc.y += __shfl_xor_sync(0xffffffffu, acc.y, off);
        acc.z += __shfl_xor_sync(0xffffffffu, acc.z, off);
        acc.w += __shfl_xor_sync(0xffffffffu, acc.w, off);
    }

    if (grp == 0) {
        const float4 bb = *(const float4*)&b1s[sub * 4];
        float4 o;
        o.x = fmaxf(acc.x + bb.x, 0.f);
        o.y = fmaxf(acc.y + bb.y, 0.f);
        o.z = fmaxf(acc.z + bb.z, 0.f);
        o.w = fmaxf(acc.w + bb.w, 0.f);
        // pad features (25..31): acc=0, b=0 -> 0  ✓
        ((float4*)g_ap)[(size_t)i * 8 + sub] = o;
    }
}

// ---------------------------------------------------------------------------
// Layer-2 aggregate (same grouped-float4) + GEMM2 + b2 + log-softmax.
#define WPB2 8
__global__ void agg2_kernel(float* __restrict__ out,
                            const float* __restrict__ W2,
                            const float* __restrict__ b2, int N) {
    __shared__ float w2s[H1 * C2];
    __shared__ float b2s[C2];
    __shared__ __align__(16) float sa[WPB2][32];
    for (int k = threadIdx.x; k < H1 * C2; k += WPB2 * 32) w2s[k] = W2[k];
    if (threadIdx.x < C2) b2s[threadIdx.x] = b2[threadIdx.x];
    __syncthreads();

    int warp = threadIdx.x >> 5;
    int lane = threadIdx.x & 31;
    int grp  = lane >> 3;
    int sub  = lane & 7;
    int i = blockIdx.x * WPB2 + warp;
    if (i >= N) return;

    const float4* a4 = (const float4*)g_ap;
    float4 acc = make_float4(0.f, 0.f, 0.f, 0.f);
    if (grp == 0) {
        float dv = g_dinv[i];
        float d2 = dv * dv;
        float4 sv = __ldg(&a4[(size_t)i * 8 + sub]);
        acc.x = d2 * sv.x; acc.y = d2 * sv.y; acc.z = d2 * sv.z; acc.w = d2 * sv.w;
    }

    int j0 = g_row[i], j1 = g_row[i + 1];
    for (int jb = j0; jb < j1; jb += 4) {
        int je = jb + grp;
        int2 pr = (je < j1) ? __ldg(&g_edge[je]) : make_int2(0, 0);
        float nm = __int_as_float(pr.y);
        float4 v = __ldg(&a4[(size_t)pr.x * 8 + sub]);
        acc.x += nm * v.x; acc.y += nm * v.y;
        acc.z += nm * v.z; acc.w += nm * v.w;
    }

    #pragma unroll
    for (int off = 8; off <= 16; off <<= 1) {
        acc.x += __shfl_xor_sync(0xffffffffu, acc.x, off);
        acc.y += __shfl_xor_sync(0xffffffffu, acc.y, off);
        acc.z += __shfl_xor_sync(0xffffffffu, acc.z, off);
        acc.w += __shfl_xor_sync(0xffffffffu, acc.w, off);
    }

    if (grp == 0) *(float4*)&sa[warp][sub * 4] = acc;
    __syncwarp();

    const float* a = sa[warp];
    bool has1 = (lane < C2 - 32);
    float o0 = b2s[lane];
    float o1 = has1 ? b2s[lane + 32] : 0.0f;
    #pragma unroll
    for (int k = 0; k < H1; k++) {
        float av = a[k];
        o0 += av * w2s[k * C2 + lane];
        if (has1) o1 += av * w2s[k * C2 + lane + 32];
    }

    float m = fmaxf(o0, has1 ? o1 : -3.4e38f);
    #pragma unroll
    for (int off = 16; off > 0; off >>= 1)
        m = fmaxf(m, __shfl_xor_sync(0xffffffffu, m, off));
    float s = __expf(o0 - m) + (has1 ? __expf(o1 - m) : 0.0f);
    #pragma unroll
    for (int off = 16; off > 0; off >>= 1)
        s += __shfl_xor_sync(0xffffffffu, s, off);
    float lse = m + logf(s);

    out[(size_t)i * C2 + lane] = o0 - lse;
    if (has1) out[(size_t)i * C2 + 32 + lane] = o1 - lse;
}

// ---------------------------------------------------------------------------
extern "C" void kernel_launch(void* const* d_in, const int* in_sizes, int n_in,
                              void* d_out, int out_size) {
    const float* x    = (const float*)d_in[0];
    const int*   ei32 = (const int*)d_in[1];
    const float* w    = (const float*)d_in[2];
    const float* W1   = (const float*)d_in[3];
    const float* b1   = (const float*)d_in[4];
    const float* W2   = (const float*)d_in[5];
    const float* b2   = (const float*)d_in[6];
    float* out = (float*)d_out;

    int E = in_sizes[2];
    int N = in_sizes[0] / FIN;

    const int TB = 256;
    int gridE = (E + TB - 1) / TB;
    int gridN = (N + TB - 1) / TB;
    int NB    = (N + 1023) / 1024;
    int gridW = (N + 7) / 8;

    int half = ((N / 2) + G1_RPB - 1) / G1_RPB * G1_RPB;   // row-block aligned
    int g1a  = half / G1_RPB;
    int g1b  = (N - half + G1_RPB - 1) / G1_RPB;

    detect_init_kernel<<<gridN, TB>>>(ei32, N);                    // #0
    gemm1_kernel<<<g1a, G1_TB>>>(x, W1, 0, half);                  // #1
    gemm1_kernel<<<g1b, G1_TB>>>(x, W1, half, N);                  // #2
    degree_kernel<<<gridE, TB>>>(ei32, w, E);                      // #3 <- ncu
    dinv_kernel<<<gridN, TB>>>(N);                                 // #4
    scan_local<<<NB, 1024>>>(N);                                   // #5
    scan_tops<<<1, 128>>>(NB, N, E);                               // #6
    scan_add<<<gridN, TB>>>(N);                                    // #7
    build_kernel<<<gridE, TB>>>(ei32, w, E);                       // #8
    agg1_kernel<<<gridW, WPB1 * 32>>>(b1, N);                      // #9
    agg2_kernel<<<gridW, WPB2 * 32>>>(out, W2, b2, N);             // #10
}

// round 15
// speedup vs baseline: 1.1288x; 1.0460x over previous
#include <cuda_runtime.h>
#include <cuda_bf16.h>

// Problem constants: N=100000, E=3200000, F_in=128, H=25, C=40
#define MAXN 100000
#define MAXE 3200000
#define FIN  128
#define H1   25
#define H1P  32        // padded pitch: 128B rows (h1p, ap) = 8 float4
#define C2   40

// Scratch (__device__ globals — allocation-free rule; zero-init at load)
__device__ float g_dinv[MAXN];
__device__ int   g_cnt [MAXN];
__device__ int   g_row [MAXN + 1];
__device__ int   g_cur [MAXN];
__device__ int   g_psum[128];
__device__ int   g_poff[128];
__device__ int2  g_edge[MAXE];         // {src, float_bits(w)} — RAW weight, no norm
__device__ float g_h1p [MAXN * H1P];   // gemm1: x@W1; after degscale: dinv*(x@W1)
__device__ float g_ap  [MAXN * H1P];   // dinv * relu(dinv*acc + b1), pads 0
__device__ int   g_is64;

// ---------------------------------------------------------------------------
// launch #0: detect dtype + init cnt
__global__ void detect_init_kernel(const int* __restrict__ ei, int N) {
    int i = blockIdx.x * blockDim.x + threadIdx.x;
    if (i < N) g_cnt[i] = 0;
    if (blockIdx.x == 0 && threadIdx.x == 0) {
        int all0 = 1;
        for (int k = 0; k < 64; k++)
            if (ei[2 * k + 1] != 0) { all0 = 0; break; }
        g_is64 = all0;
    }
}

__device__ __forceinline__ int ld_node(const int* __restrict__ ei32,
                                       long long pos, int is64) {
    return ei32[is64 ? (pos << 1) : pos];   // little-endian low word
}

// launch #3 (ncu slot): in-degree histogram — ONE int atomic per edge
__global__ void cnt_kernel(const int* __restrict__ ei32, int E) {
    int e = blockIdx.x * blockDim.x + threadIdx.x;
    if (e >= E) return;
    int d = ld_node(ei32, (long long)E + e, g_is64);
    atomicAdd(&g_cnt[d], 1);
}

// ---------------------------------------------------------------------------
// 3-phase scan of g_cnt -> g_row (exclusive), g_cur copy, g_row[N]=E.
__global__ void scan_local(int N) {
    __shared__ int sh[1024];
    int i = blockIdx.x * 1024 + threadIdx.x;
    int v = (i < N) ? g_cnt[i] : 0;
    sh[threadIdx.x] = v;
    __syncthreads();
    int acc = v;
    for (int off = 1; off < 1024; off <<= 1) {
        int p = (threadIdx.x >= off) ? sh[threadIdx.x - off] : 0;
        __syncthreads();
        acc += p;
        sh[threadIdx.x] = acc;
        __syncthreads();
    }
    if (i < N) g_row[i] = acc - v;
    if (threadIdx.x == 1023) g_psum[blockIdx.x] = acc;
}

__global__ void scan_tops(int NB, int N, int E) {
    __shared__ int sh[128];
    int t = threadIdx.x;
    int v = (t < NB) ? g_psum[t] : 0;
    sh[t] = v;
    __syncthreads();
    int acc = v;
    for (int off = 1; off < 128; off <<= 1) {
        int p = (t >= off) ? sh[t - off] : 0;
        __syncthreads();
        acc += p;
        sh[t] = acc;
        __syncthreads();
    }
    if (t < NB) g_poff[t] = acc - v;
    if (t == 0) g_row[N] = E;
}

__global__ void scan_add(int N) {
    int i = blockIdx.x * blockDim.x + threadIdx.x;
    if (i >= N) return;
    int r = g_row[i] + g_poff[i >> 10];
    g_row[i] = r;
    g_cur[i] = r;
}

// Bucket-scatter RAW edges {src, w}. No dinv reads at all.
__global__ void build_kernel(const int* __restrict__ ei32,
                             const float* __restrict__ w, int E) {
    int e = blockIdx.x * blockDim.x + threadIdx.x;
    if (e >= E) return;
    int is64 = g_is64;
    int s = ld_node(ei32, e, is64);
    int d = ld_node(ei32, (long long)E + e, is64);
    int pos = atomicAdd(&g_cur[d], 1);
    g_edge[pos] = make_int2(s, __float_as_int(w[e]));
}

// Streaming degree + h1p row scaling. Warp per node:
// dv = rsqrt(sum(w)+1); g_dinv[i]=dv; h1p[i,:] *= dv (32 lanes = 32 floats).
#define WPBD 8
__global__ void degscale_kernel(int N) {
    int warp = threadIdx.x >> 5;
    int lane = threadIdx.x & 31;
    int i = blockIdx.x * WPBD + warp;
    if (i >= N) return;
    int j0 = g_row[i], j1 = g_row[i + 1];
    float s = 0.0f;
    for (int j = j0 + lane; j < j1; j += 32)
        s += __int_as_float(__ldg(&g_edge[j]).y);
    #pragma unroll
    for (int off = 16; off > 0; off >>= 1)
        s += __shfl_xor_sync(0xffffffffu, s, off);
    float dv = rsqrtf(s + 1.0f);          // all lanes have s
    if (lane == 0) g_dinv[i] = dv;
    g_h1p[(size_t)i * H1P + lane] *= dv;  // pads stay 0
}

// ---------------------------------------------------------------------------
// GEMM1: h1p[rows r0..r1) = x @ W1 (unscaled here). Split-launch.
#define G1_TB   320
#define G1_RPB  256
__global__ void gemm1_kernel(const float* __restrict__ x,
                             const float* __restrict__ W1, int r_base, int r_end) {
    __shared__ float ws[FIN * H1];
    for (int i = threadIdx.x; i < FIN * H1; i += G1_TB) ws[i] = W1[i];
    __syncthreads();

    int rowGroup = threadIdx.x / 5;
    int colGroup = threadIdx.x % 5;
    int r0 = r_base + blockIdx.x * G1_RPB + rowGroup * 4;
    int c0 = colGroup * 5;

    float acc[4][5];
    #pragma unroll
    for (int a = 0; a < 4; a++)
        #pragma unroll
        for (int b = 0; b < 5; b++) acc[a][b] = 0.0f;

    #pragma unroll 4
    for (int kb = 0; kb < FIN / 4; kb++) {
        float xr[4][4];
        #pragma unroll
        for (int a = 0; a < 4; a++) {
            int r = r0 + a;
            float4 v = (r < r_end) ? __ldg((const float4*)(x + (size_t)r * FIN) + kb)
                                   : make_float4(0.f, 0.f, 0.f, 0.f);
            xr[a][0] = v.x; xr[a][1] = v.y; xr[a][2] = v.z; xr[a][3] = v.w;
        }
        #pragma unroll
        for (int t = 0; t < 4; t++) {
            int k = kb * 4 + t;
            float wv[5];
            #pragma unroll
            for (int b = 0; b < 5; b++) wv[b] = ws[k * H1 + c0 + b];
            #pragma unroll
            for (int a = 0; a < 4; a++)
                #pragma unroll
                for (int b = 0; b < 5; b++) acc[a][b] += xr[a][t] * wv[b];
        }
    }

    #pragma unroll
    for (int a = 0; a < 4; a++) {
        int r = r0 + a;
        if (r >= r_end) break;
        #pragma unroll
        for (int b = 0; b < 5; b++)
            g_h1p[(size_t)r * H1P + c0 + b] = acc[a][b];
    }
}

// ---------------------------------------------------------------------------
// Layer-1 aggregate (grouped-float4). h1p holds h' = dinv*h.
// acc = h'_i + sum_j w_j h'_sj ; ap' = dinv_i * relu(dinv_i*acc + b1).
#define WPB1 8
__global__ void agg1_kernel(const float* __restrict__ b1, int N) {
    __shared__ __align__(16) float b1s[32];
    if (threadIdx.x < 32)
        b1s[threadIdx.x] = (threadIdx.x < H1) ? b1[threadIdx.x] : 0.0f;
    __syncthreads();

    int warp = threadIdx.x >> 5;
    int lane = threadIdx.x & 31;
    int grp  = lane >> 3;        // edge group 0..3
    int sub  = lane & 7;         // feature quad 0..7
    int i = blockIdx.x * WPB1 + warp;
    if (i >= N) return;

    const float4* h4 = (const float4*)g_h1p;
    float4 acc = make_float4(0.f, 0.f, 0.f, 0.f);
    if (grp == 0) acc = __ldg(&h4[(size_t)i * 8 + sub]);   // self term h'_i

    int j0 = g_row[i], j1 = g_row[i + 1];
    for (int jb = j0; jb < j1; jb += 4) {
        int je = jb + grp;
        int2 pr = (je < j1) ? __ldg(&g_edge[je]) : make_int2(0, 0);
        float wv = __int_as_float(pr.y);                    // raw w; 0 for OOB
        float4 v = __ldg(&h4[(size_t)pr.x * 8 + sub]);
        acc.x += wv * v.x; acc.y += wv * v.y;
        acc.z += wv * v.z; acc.w += wv * v.w;
    }

    #pragma unroll
    for (int off = 8; off <= 16; off <<= 1) {
        acc.x += __shfl_xor_sync(0xffffffffu, acc.x, off);
        acc.y += __shfl_xor_sync(0xffffffffu, acc.y, off);
        acc.z += __shfl_xor_sync(0xffffffffu, acc.z, off);
        acc.w += __shfl_xor_sync(0xffffffffu, acc.w, off);
    }

    if (grp == 0) {
        float dv = g_dinv[i];
        const float4 bb = *(const float4*)&b1s[sub * 4];
        float4 o;
        o.x = dv * fmaxf(dv * acc.x + bb.x, 0.f);
        o.y = dv * fmaxf(dv * acc.y + bb.y, 0.f);
        o.z = dv * fmaxf(dv * acc.z + bb.z, 0.f);
        o.w = dv * fmaxf(dv * acc.w + bb.w, 0.f);
        ((float4*)g_ap)[(size_t)i * 8 + sub] = o;           // pads: 0
    }
}

// ---------------------------------------------------------------------------
// Layer-2 aggregate (grouped-float4) on ap' + GEMM2 + b2 + log-softmax.
// pre = dinv_i * (ap'_i + sum_j w_j ap'_sj); out = logsoftmax(pre@W2 + b2).
#define WPB2 8
__global__ void agg2_kernel(float* __restrict__ out,
                            const float* __restrict__ W2,
                            const float* __restrict__ b2, int N) {
    __shared__ float w2s[H1 * C2];
    __shared__ float b2s[C2];
    __shared__ __align__(16) float sa[WPB2][32];
    for (int k = threadIdx.x; k < H1 * C2; k += WPB2 * 32) w2s[k] = W2[k];
    if (threadIdx.x < C2) b2s[threadIdx.x] = b2[threadIdx.x];
    __syncthreads();

    int warp = threadIdx.x >> 5;
    int lane = threadIdx.x & 31;
    int grp  = lane >> 3;
    int sub  = lane & 7;
    int i = blockIdx.x * WPB2 + warp;
    if (i >= N) return;

    const float4* a4 = (const float4*)g_ap;
    float4 acc = make_float4(0.f, 0.f, 0.f, 0.f);
    if (grp == 0) acc = __ldg(&a4[(size_t)i * 8 + sub]);   // self term ap'_i

    int j0 = g_row[i], j1 = g_row[i + 1];
    for (int jb = j0; jb < j1; jb += 4) {
        int je = jb + grp;
        int2 pr = (je < j1) ? __ldg(&g_edge[je]) : make_int2(0, 0);
        float wv = __int_as_float(pr.y);
        float4 v = __ldg(&a4[(size_t)pr.x * 8 + sub]);
        acc.x += wv * v.x; acc.y += wv * v.y;
        acc.z += wv * v.z; acc.w += wv * v.w;
    }

    #pragma unroll
    for (int off = 8; off <= 16; off <<= 1) {
        acc.x += __shfl_xor_sync(0xffffffffu, acc.x, off);
        acc.y += __shfl_xor_sync(0xffffffffu, acc.y, off);
        acc.z += __shfl_xor_sync(0xffffffffu, acc.z, off);
        acc.w += __shfl_xor_sync(0xffffffffu, acc.w, off);
    }

    if (grp == 0) {
        float dv = g_dinv[i];
        float4 o;
        o.x = dv * acc.x; o.y = dv * acc.y;
        o.z = dv * acc.z; o.w = dv * acc.w;
        *(float4*)&sa[warp][sub * 4] = o;
    }
    __syncwarp();

    const float* a = sa[warp];
    bool has1 = (lane < C2 - 32);
    float o0 = b2s[lane];
    float o1 = has1 ? b2s[lane + 32] : 0.0f;
    #pragma unroll
    for (int k = 0; k < H1; k++) {
        float av = a[k];
        o0 += av * w2s[k * C2 + lane];
        if (has1) o1 += av * w2s[k * C2 + lane + 32];
    }

    float m = fmaxf(o0, has1 ? o1 : -3.4e38f);
    #pragma unroll
    for (int off = 16; off > 0; off >>= 1)
        m = fmaxf(m, __shfl_xor_sync(0xffffffffu, m, off));
    float s = __expf(o0 - m) + (has1 ? __expf(o1 - m) : 0.0f);
    #pragma unroll
    for (int off = 16; off > 0; off >>= 1)
        s += __shfl_xor_sync(0xffffffffu, s, off);
    float lse = m + logf(s);

    out[(size_t)i * C2 + lane] = o0 - lse;
    if (has1) out[(size_t)i * C2 + 32 + lane] = o1 - lse;
}

// ---------------------------------------------------------------------------
extern "C" void kernel_launch(void* const* d_in, const int* in_sizes, int n_in,
                              void* d_out, int out_size) {
    const float* x    = (const float*)d_in[0];
    const int*   ei32 = (const int*)d_in[1];
    const float* w    = (const float*)d_in[2];
    const float* W1   = (const float*)d_in[3];
    const float* b1   = (const float*)d_in[4];
    const float* W2   = (const float*)d_in[5];
    const float* b2   = (const float*)d_in[6];
    float* out = (float*)d_out;

    int E = in_sizes[2];
    int N = in_sizes[0] / FIN;

    const int TB = 256;
    int gridE = (E + TB - 1) / TB;
    int gridN = (N + TB - 1) / TB;
    int NB    = (N + 1023) / 1024;
    int gridW = (N + 7) / 8;

    int half = ((N / 2) + G1_RPB - 1) / G1_RPB * G1_RPB;
    int g1a  = half / G1_RPB;
    int g1b  = (N - half + G1_RPB - 1) / G1_RPB;

    detect_init_kernel<<<gridN, TB>>>(ei32, N);                    // #0
    gemm1_kernel<<<g1a, G1_TB>>>(x, W1, 0, half);                  // #1
    gemm1_kernel<<<g1b, G1_TB>>>(x, W1, half, N);                  // #2
    cnt_kernel<<<gridE, TB>>>(ei32, E);                            // #3 <- ncu
    scan_local<<<NB, 1024>>>(N);                                   // #4
    scan_tops<<<1, 128>>>(NB, N, E);                               // #5
    scan_add<<<gridN, TB>>>(N);                                    // #6
    build_kernel<<<gridE, TB>>>(ei32, w, E);                       // #7
    degscale_kernel<<<gridW, WPBD * 32>>>(N);                      // #8
    agg1_kernel<<<gridW, WPB1 * 32>>>(b1, N);                      // #9
    agg2_kernel<<<gridW, WPB2 * 32>>>(out, W2, b2, N);             // #10
}